// round 1
// baseline (speedup 1.0000x reference)
#include <cuda_runtime.h>
#include <math.h>

// Problem constants (fixed by the dataset)
#define NDIM 8192
#define RANK 64

// Quad-kernel tiling
#define BM 128
#define BK 32
#define KSPLIT 8
#define QTHREADS 128
#define TM 8
#define TN 8

// Scratch (allocation-free rule: __device__ globals)
__device__ double g_acc[3];                 // [0]=E1 sum, [1]=quad_U, [2]=quad_V
__device__ float  g_Vt[NDIM * RANK];        // V transposed to [8192, 64]

// ---- packed f32x2 helpers (sm_100+ FFMA2) ----
__device__ __forceinline__ unsigned long long pack2(float x, float y) {
    unsigned long long r;
    asm("mov.b64 %0, {%1, %2};" : "=l"(r) : "f"(x), "f"(y));
    return r;
}
__device__ __forceinline__ float2 unpack2(unsigned long long r) {
    float2 v;
    asm("mov.b64 {%0, %1}, %2;" : "=f"(v.x), "=f"(v.y) : "l"(r));
    return v;
}
__device__ __forceinline__ void ffma2(unsigned long long& c,
                                      unsigned long long a,
                                      unsigned long long b) {
    asm("fma.rn.f32x2 %0, %1, %2, %0;" : "+l"(c) : "l"(a), "l"(b));
}

// ---- 1) zero the accumulators (runs every call: deterministic) ----
__global__ void zero_kernel() {
    if (threadIdx.x < 3) g_acc[threadIdx.x] = 0.0;
}

// ---- 2) transpose V [64, 8192] -> g_Vt [8192, 64] ----
__global__ void transpose_kernel(const float* __restrict__ V) {
    __shared__ float tile[32][33];
    int x = blockIdx.x * 32 + threadIdx.x;   // n (0..8191)
    int y = blockIdx.y * 32 + threadIdx.y;   // r (0..63)
    tile[threadIdx.y][threadIdx.x] = V[(size_t)y * NDIM + x];
    __syncthreads();
    int n = blockIdx.x * 32 + threadIdx.y;
    int r = blockIdx.y * 32 + threadIdx.x;
    g_Vt[(size_t)n * RANK + r] = tile[threadIdx.x][threadIdx.y];
}

// ---- 3) E1: sum_n (vals - U[row]·Vt[col])^2 ----
__global__ void e1_kernel(const float* __restrict__ vals,
                          const int* __restrict__ rows,
                          const int* __restrict__ cols,
                          const float* __restrict__ U, int n) {
    float local = 0.f;
    for (int i = blockIdx.x * blockDim.x + threadIdx.x; i < n;
         i += gridDim.x * blockDim.x) {
        int r = rows[i], c = cols[i];
        const float4* u4 = (const float4*)(U + (size_t)r * RANK);
        const float4* v4 = (const float4*)(g_Vt + (size_t)c * RANK);
        float s = 0.f;
        #pragma unroll
        for (int k = 0; k < RANK / 4; k++) {
            float4 a = u4[k];
            float4 b = v4[k];
            s = fmaf(a.x, b.x, s);
            s = fmaf(a.y, b.y, s);
            s = fmaf(a.z, b.z, s);
            s = fmaf(a.w, b.w, s);
        }
        float d = vals[i] - s;
        local = fmaf(d, d, local);
    }
    // warp + block reduce
    #pragma unroll
    for (int o = 16; o; o >>= 1) local += __shfl_xor_sync(0xffffffffu, local, o);
    __shared__ float warpsum[8];
    int lane = threadIdx.x & 31, w = threadIdx.x >> 5;
    if (lane == 0) warpsum[w] = local;
    __syncthreads();
    if (threadIdx.x == 0) {
        float s = 0.f;
        #pragma unroll
        for (int i = 0; i < 8; i++) s += warpsum[i];
        atomicAdd(&g_acc[0], (double)s);
    }
}

// ---- 4) quad: sum_{i,j} S[i,j] * dot(X[i,:], X[j,:]) for both (S_U,U) & (S_V,Vt)
// Structured as GEMM Y[i,r] = sum_j S[i,j] X[j,r] over a K-chunk, fused with
// the epilogue dot sum_i Y[i,:]·X[i,:] (linear in j, so K-split partials add).
__global__ __launch_bounds__(QTHREADS) void quad_kernel(
    const float* __restrict__ S_U, const float* __restrict__ U,
    const float* __restrict__ S_V) {
    __shared__ float sS[BM][BK + 1];   // padded: conflict-free column reads
    __shared__ float sX[BK][RANK];

    const float* S;
    const float* X;
    int slot;
    if (blockIdx.z == 0) { S = S_U; X = U;    slot = 1; }
    else                 { S = S_V; X = g_Vt; slot = 2; }

    const int i0 = blockIdx.x * BM;
    const int kchunk = NDIM / KSPLIT;            // 1024
    const int kbeg = blockIdx.y * kchunk;
    const int t = threadIdx.x;
    const int tx = t & 7;    // N (rank) direction, 8 threads * TN=8 = 64
    const int ty = t >> 3;   // M direction, 16 threads * TM=8 = 128

    unsigned long long acc[TM][TN / 2];
    #pragma unroll
    for (int i = 0; i < TM; i++)
        #pragma unroll
        for (int j = 0; j < TN / 2; j++) acc[i][j] = 0ULL;

    for (int k0 = kbeg; k0 < kbeg + kchunk; k0 += BK) {
        // load S tile: BM x BK = 1024 float4, 128 threads -> 8 passes
        #pragma unroll
        for (int p = 0; p < (BM * BK) / (4 * QTHREADS); p++) {
            int flat = p * QTHREADS + t;
            int row = flat >> 3;
            int c4 = (flat & 7) << 2;
            float4 v = *(const float4*)(S + (size_t)(i0 + row) * NDIM + k0 + c4);
            sS[row][c4 + 0] = v.x;
            sS[row][c4 + 1] = v.y;
            sS[row][c4 + 2] = v.z;
            sS[row][c4 + 3] = v.w;
        }
        // load X tile: BK x RANK = 512 float4, 128 threads -> 4 passes
        #pragma unroll
        for (int p = 0; p < (BK * RANK) / (4 * QTHREADS); p++) {
            int flat = p * QTHREADS + t;
            int row = flat >> 4;
            int c4 = (flat & 15) << 2;
            *(float4*)&sX[row][c4] =
                *(const float4*)(X + (size_t)(k0 + row) * RANK + c4);
        }
        __syncthreads();

        #pragma unroll
        for (int kk = 0; kk < BK; kk++) {
            unsigned long long b[TN / 2];
            float4 b0 = *(const float4*)&sX[kk][tx * TN];
            float4 b1 = *(const float4*)&sX[kk][tx * TN + 4];
            b[0] = pack2(b0.x, b0.y);
            b[1] = pack2(b0.z, b0.w);
            b[2] = pack2(b1.x, b1.y);
            b[3] = pack2(b1.z, b1.w);
            #pragma unroll
            for (int mi = 0; mi < TM; mi++) {
                float a = sS[ty * TM + mi][kk];
                unsigned long long a2 = pack2(a, a);
                #pragma unroll
                for (int q = 0; q < TN / 2; q++) ffma2(acc[mi][q], a2, b[q]);
            }
        }
        __syncthreads();
    }

    // fused epilogue: partial += acc[i,:] · X[i0+row, :]
    float partial = 0.f;
    #pragma unroll
    for (int mi = 0; mi < TM; mi++) {
        const float* xr = X + (size_t)(i0 + ty * TM + mi) * RANK + tx * TN;
        #pragma unroll
        for (int q = 0; q < TN / 2; q++) {
            float2 a = unpack2(acc[mi][q]);
            partial = fmaf(a.x, xr[2 * q], partial);
            partial = fmaf(a.y, xr[2 * q + 1], partial);
        }
    }
    #pragma unroll
    for (int o = 16; o; o >>= 1)
        partial += __shfl_xor_sync(0xffffffffu, partial, o);
    __shared__ float wsum[QTHREADS / 32];
    if ((t & 31) == 0) wsum[t >> 5] = partial;
    __syncthreads();
    if (t == 0) {
        float s = 0.f;
        #pragma unroll
        for (int i = 0; i < QTHREADS / 32; i++) s += wsum[i];
        atomicAdd(&g_acc[slot], (double)s);
    }
}

// ---- 5) finalize scalar ----
__global__ void finalize_kernel(const float* __restrict__ sigma,
                                float* __restrict__ out, int nobs) {
    double s2 = (double)sigma[0] * (double)sigma[0];
    double E = g_acc[0] / (2.0 * s2) + 0.5 * (g_acc[1] + g_acc[2]) +
               (double)nobs * log(s2);
    out[0] = (float)E;
}

extern "C" void kernel_launch(void* const* d_in, const int* in_sizes, int n_in,
                              void* d_out, int out_size) {
    const float* vals  = (const float*)d_in[0];
    const int*   rows  = (const int*)d_in[1];
    const int*   cols  = (const int*)d_in[2];
    const float* U     = (const float*)d_in[3];
    const float* V     = (const float*)d_in[4];
    const float* sigma = (const float*)d_in[5];
    const float* S_U   = (const float*)d_in[6];
    const float* S_V   = (const float*)d_in[7];
    int nobs = in_sizes[0];
    float* out = (float*)d_out;

    zero_kernel<<<1, 32>>>();
    transpose_kernel<<<dim3(NDIM / 32, RANK / 32), dim3(32, 32)>>>(V);
    e1_kernel<<<1024, 256>>>(vals, rows, cols, U, nobs);
    quad_kernel<<<dim3(NDIM / BM, KSPLIT, 2), QTHREADS>>>(S_U, U, S_V);
    finalize_kernel<<<1, 1>>>(sigma, out, nobs);
}

// round 3
// speedup vs baseline: 2.1184x; 2.1184x over previous
#include <cuda_runtime.h>
#include <cuda_bf16.h>
#include <cstdint>
#include <math.h>

#define NDIM 8192
#define RANK 64
#define BM 128
#define BKC 64
#define NCH (NDIM / BKC)       // 128 K-chunks
#define QTHREADS 256
// padded tiles: A 128 rows x 144B, B 64 rows x 144B, double buffered
#define A_TILE (BM * 144)
#define B_TILE (RANK * 144)
#define QSMEM (1024 + 2 * (A_TILE + B_TILE))

// ---- device scratch (allocation-free rule) ----
__device__ double g_acc[3];                    // [0]=E1, [1]=quad_U, [2]=quad_V
__device__ float  g_Vt[NDIM * RANK];           // V^T fp32 [8192,64]
__device__ __nv_bfloat16 g_Bu[RANK * NDIM];    // U^T bf16 [64,8192]
__device__ __nv_bfloat16 g_Bv[RANK * NDIM];    // V   bf16 [64,8192]

__device__ __forceinline__ uint32_t smem_u32(const void* p) {
    uint32_t a;
    asm("{ .reg .u64 t; cvta.to.shared.u64 t, %1; cvt.u32.u64 %0, t; }"
        : "=r"(a) : "l"(p));
    return a;
}

// ======================= small kernels =======================
__global__ void zero_kernel() {
    if (threadIdx.x < 3) g_acc[threadIdx.x] = 0.0;
}

// V [64,8192] -> g_Vt fp32 [8192,64]
__global__ void transpose_kernel(const float* __restrict__ V) {
    __shared__ float tile[32][33];
    int x = blockIdx.x * 32 + threadIdx.x;
    int y = blockIdx.y * 32 + threadIdx.y;
    tile[threadIdx.y][threadIdx.x] = V[(size_t)y * NDIM + x];
    __syncthreads();
    int n = blockIdx.x * 32 + threadIdx.y;
    int r = blockIdx.y * 32 + threadIdx.x;
    g_Vt[(size_t)n * RANK + r] = tile[threadIdx.x][threadIdx.y];
}

// V fp32 [64,8192] -> g_Bv bf16 (elementwise)
__global__ void convV_kernel(const float* __restrict__ V) {
    int i = (blockIdx.x * blockDim.x + threadIdx.x) * 4;
    float4 v = *(const float4*)(V + i);
    *(__nv_bfloat162*)(g_Bv + i)     = __floats2bfloat162_rn(v.x, v.y);
    *(__nv_bfloat162*)(g_Bv + i + 2) = __floats2bfloat162_rn(v.z, v.w);
}

// U [8192,64] fp32 -> g_Bu bf16 [64,8192]
__global__ void transU_kernel(const float* __restrict__ U) {
    __shared__ float tile[32][33];
    int i0 = blockIdx.x * 32, r0 = blockIdx.y * 32;
    tile[threadIdx.y][threadIdx.x] =
        U[(size_t)(i0 + threadIdx.y) * RANK + r0 + threadIdx.x];
    __syncthreads();
    g_Bu[(size_t)(r0 + threadIdx.y) * NDIM + i0 + threadIdx.x] =
        __float2bfloat16(tile[threadIdx.x][threadIdx.y]);
}

// E1: sum_n (vals - U[row]·Vt[col])^2
__global__ void e1_kernel(const float* __restrict__ vals,
                          const int* __restrict__ rows,
                          const int* __restrict__ cols,
                          const float* __restrict__ U, int n) {
    float local = 0.f;
    for (int i = blockIdx.x * blockDim.x + threadIdx.x; i < n;
         i += gridDim.x * blockDim.x) {
        int r = rows[i], c = cols[i];
        const float4* u4 = (const float4*)(U + (size_t)r * RANK);
        const float4* v4 = (const float4*)(g_Vt + (size_t)c * RANK);
        float s = 0.f;
        #pragma unroll
        for (int k = 0; k < RANK / 4; k++) {
            float4 a = u4[k];
            float4 b = v4[k];
            s = fmaf(a.x, b.x, s);
            s = fmaf(a.y, b.y, s);
            s = fmaf(a.z, b.z, s);
            s = fmaf(a.w, b.w, s);
        }
        float d = vals[i] - s;
        local = fmaf(d, d, local);
    }
    #pragma unroll
    for (int o = 16; o; o >>= 1) local += __shfl_xor_sync(0xffffffffu, local, o);
    __shared__ float warpsum[8];
    int lane = threadIdx.x & 31, w = threadIdx.x >> 5;
    if (lane == 0) warpsum[w] = local;
    __syncthreads();
    if (threadIdx.x == 0) {
        float s = 0.f;
        #pragma unroll
        for (int i = 0; i < 8; i++) s += warpsum[i];
        atomicAdd(&g_acc[0], (double)s);
    }
}

// ======================= quad via mma.sync (HMMA bf16) =======================
// Per CTA: 128 S-rows, K loop 8192 in 64-col chunks.
// A = S tile fp32->bf16 in-flight; B = X^T bf16 (precomputed scratch).
// Each warp: 16 M-rows x 64 N. Accumulate fp32 in registers, fused epilogue.
__global__ __launch_bounds__(QTHREADS, 1) void quad_mma_kernel(
    const float* __restrict__ S_U, const float* __restrict__ U,
    const float* __restrict__ S_V) {
    extern __shared__ char dynsmem[];
    __shared__ float wsum[QTHREADS / 32];

    const int t = threadIdx.x;
    const int wid = t >> 5, lane = t & 31;

    const float* S;
    const __nv_bfloat16* Bg;
    const float* Xf;
    int slot;
    if (blockIdx.z == 0) { S = S_U; Bg = g_Bu; Xf = U;    slot = 1; }
    else                 { S = S_V; Bg = g_Bv; Xf = g_Vt; slot = 2; }
    const int i0 = blockIdx.x * BM;

    uint32_t base = (smem_u32(dynsmem) + 1023u) & ~1023u;
    uint32_t Abuf[2] = { base, base + A_TILE };
    uint32_t Bbuf[2] = { base + 2 * A_TILE, base + 2 * A_TILE + B_TILE };

    // ---- per-thread staging coordinates ----
    // A: 128x64 fp32 -> bf16. 8 passes of 256 thr, each 4 floats (8B bf16).
    uint32_t a_sts[8];
    const float* a_ldg[8];
    #pragma unroll
    for (int p = 0; p < 8; p++) {
        int flat = p * QTHREADS + t;
        int row = flat >> 4;                 // 16 thr/row
        int c = (flat & 15) * 4;             // float col
        a_sts[p] = row * 144 + (flat & 15) * 8;
        a_ldg[p] = S + (size_t)(i0 + row) * NDIM + c;
    }
    // B: 64x64 bf16 = 8KB. 2 passes of 256 thr, each 16B.
    uint32_t b_sts[2];
    const __nv_bfloat16* b_ldg[2];
    #pragma unroll
    for (int p = 0; p < 2; p++) {
        int flat = p * QTHREADS + t;
        int row = flat >> 3;                 // 8 x 16B per row
        int c16 = (flat & 7) * 16;           // byte col
        b_sts[p] = row * 144 + c16;
        b_ldg[p] = Bg + (size_t)row * NDIM + c16 / 2;
    }

    // ldmatrix lane offsets (within a tile buffer)
    const uint32_t a_lm = (uint32_t)(wid * 16 + (lane & 15)) * 144 + (lane & 16);
    const uint32_t b_lm = (uint32_t)((lane & 7) + ((lane & 16) >> 1)) * 144 +
                          ((lane & 8) << 1);

    float acc[8][4];
    #pragma unroll
    for (int tn = 0; tn < 8; tn++)
        #pragma unroll
        for (int q = 0; q < 4; q++) acc[tn][q] = 0.f;

    float4 rA[8];
    uint4  rB[2];

#define LOADC(k0) do {                                                        \
    _Pragma("unroll") for (int p = 0; p < 8; p++)                             \
        rA[p] = __ldcs((const float4*)(a_ldg[p] + (k0)));                     \
    _Pragma("unroll") for (int p = 0; p < 2; p++)                             \
        rB[p] = *(const uint4*)(b_ldg[p] + (k0));                             \
} while (0)

#define STOREC(ab, bb) do {                                                   \
    _Pragma("unroll") for (int p = 0; p < 8; p++) {                           \
        uint32_t lo, hi;                                                      \
        asm("cvt.rn.bf16x2.f32 %0, %1, %2;" : "=r"(lo)                        \
            : "f"(rA[p].y), "f"(rA[p].x));                                    \
        asm("cvt.rn.bf16x2.f32 %0, %1, %2;" : "=r"(hi)                        \
            : "f"(rA[p].w), "f"(rA[p].z));                                    \
        asm volatile("st.shared.v2.b32 [%0], {%1, %2};"                       \
                     :: "r"((ab) + a_sts[p]), "r"(lo), "r"(hi));              \
    }                                                                         \
    _Pragma("unroll") for (int p = 0; p < 2; p++)                             \
        asm volatile("st.shared.v4.b32 [%0], {%1, %2, %3, %4};"               \
                     :: "r"((bb) + b_sts[p]), "r"(rB[p].x), "r"(rB[p].y),     \
                        "r"(rB[p].z), "r"(rB[p].w));                          \
} while (0)

#define COMPUTE(ab, bb) do {                                                  \
    _Pragma("unroll") for (int s = 0; s < 4; s++) {                           \
        uint32_t a[4];                                                        \
        asm volatile("ldmatrix.sync.aligned.m8n8.x4.shared.b16 "              \
                     "{%0,%1,%2,%3}, [%4];"                                   \
                     : "=r"(a[0]), "=r"(a[1]), "=r"(a[2]), "=r"(a[3])         \
                     : "r"((ab) + a_lm + s * 32));                            \
        uint32_t b[4][4];                                                     \
        _Pragma("unroll") for (int j = 0; j < 4; j++)                         \
            asm volatile("ldmatrix.sync.aligned.m8n8.x4.shared.b16 "          \
                         "{%0,%1,%2,%3}, [%4];"                               \
                         : "=r"(b[j][0]), "=r"(b[j][1]),                      \
                           "=r"(b[j][2]), "=r"(b[j][3])                       \
                         : "r"((bb) + b_lm + j * (16 * 144) + s * 32));       \
        _Pragma("unroll") for (int tn = 0; tn < 8; tn++)                      \
            asm volatile("mma.sync.aligned.m16n8k16.row.col.f32.bf16.bf16.f32 " \
                         "{%0,%1,%2,%3}, {%4,%5,%6,%7}, {%8,%9}, "            \
                         "{%0,%1,%2,%3};"                                     \
                         : "+f"(acc[tn][0]), "+f"(acc[tn][1]),                \
                           "+f"(acc[tn][2]), "+f"(acc[tn][3])                 \
                         : "r"(a[0]), "r"(a[1]), "r"(a[2]), "r"(a[3]),        \
                           "r"(b[tn >> 1][(tn & 1) * 2]),                     \
                           "r"(b[tn >> 1][(tn & 1) * 2 + 1]));                \
    }                                                                         \
} while (0)

    LOADC(0);
    STOREC(Abuf[0], Bbuf[0]);
    __syncthreads();

    for (int cc = 0; cc < NCH; cc++) {
        int cur = cc & 1, nxt = cur ^ 1;
        if (cc + 1 < NCH) LOADC((size_t)(cc + 1) * BKC);
        COMPUTE(Abuf[cur], Bbuf[cur]);
        if (cc + 1 < NCH) {
            __syncthreads();
            STOREC(Abuf[nxt], Bbuf[nxt]);
            __syncthreads();
        }
    }

    // epilogue: partial = sum over this thread's accumulator elements of
    // D[row][n] * X[row][n]
    const int g = lane >> 2, tg = lane & 3;
    const int r0 = i0 + wid * 16 + g;
    float partial = 0.f;
    #pragma unroll
    for (int tn = 0; tn < 8; tn++) {
        int n = tn * 8 + 2 * tg;
        float2 x0 = *(const float2*)(Xf + (size_t)r0 * RANK + n);
        float2 x1 = *(const float2*)(Xf + (size_t)(r0 + 8) * RANK + n);
        partial = fmaf(acc[tn][0], x0.x, partial);
        partial = fmaf(acc[tn][1], x0.y, partial);
        partial = fmaf(acc[tn][2], x1.x, partial);
        partial = fmaf(acc[tn][3], x1.y, partial);
    }
    #pragma unroll
    for (int o = 16; o; o >>= 1)
        partial += __shfl_xor_sync(0xffffffffu, partial, o);
    if (lane == 0) wsum[wid] = partial;
    __syncthreads();
    if (t == 0) {
        float s = 0.f;
        #pragma unroll
        for (int i = 0; i < QTHREADS / 32; i++) s += wsum[i];
        atomicAdd(&g_acc[slot], (double)s);
    }
#undef LOADC
#undef STOREC
#undef COMPUTE
}

// ======================= finalize =======================
__global__ void finalize_kernel(const float* __restrict__ sigma,
                                float* __restrict__ out, int nobs) {
    double s2 = (double)sigma[0] * (double)sigma[0];
    double E = g_acc[0] / (2.0 * s2) + 0.5 * (g_acc[1] + g_acc[2]) +
               (double)nobs * log(s2);
    out[0] = (float)E;
}

extern "C" void kernel_launch(void* const* d_in, const int* in_sizes, int n_in,
                              void* d_out, int out_size) {
    const float* vals  = (const float*)d_in[0];
    const int*   rows  = (const int*)d_in[1];
    const int*   cols  = (const int*)d_in[2];
    const float* U     = (const float*)d_in[3];
    const float* V     = (const float*)d_in[4];
    const float* sigma = (const float*)d_in[5];
    const float* S_U   = (const float*)d_in[6];
    const float* S_V   = (const float*)d_in[7];
    int nobs = in_sizes[0];
    float* out = (float*)d_out;

    cudaFuncSetAttribute(quad_mma_kernel,
                         cudaFuncAttributeMaxDynamicSharedMemorySize, QSMEM);

    zero_kernel<<<1, 32>>>();
    transpose_kernel<<<dim3(NDIM / 32, RANK / 32), dim3(32, 32)>>>(V);
    convV_kernel<<<(RANK * NDIM) / (256 * 4), 256>>>(V);
    transU_kernel<<<dim3(NDIM / 32, RANK / 32), dim3(32, 32)>>>(U);
    e1_kernel<<<2048, 256>>>(vals, rows, cols, U, nobs);
    quad_mma_kernel<<<dim3(NDIM / BM, 1, 2), QTHREADS, QSMEM>>>(S_U, U, S_V);
    finalize_kernel<<<1, 1>>>(sigma, out, nobs);
}

// round 4
// speedup vs baseline: 2.3781x; 1.1226x over previous
#include <cuda_runtime.h>
#include <cuda_bf16.h>
#include <cstdint>
#include <math.h>

#define NDIM 8192
#define RANK 64
#define BM 128
#define BKC 64
#define NCH (NDIM / BKC)       // 128 K-chunks
#define QTHREADS 256
#define A_TILE (BM * 144)
#define B_TILE (RANK * 144)
#define QSMEM (1024 + 2 * (A_TILE + B_TILE))

// ---- device scratch (allocation-free rule) ----
__device__ double g_acc[3];                     // [0]=E1, [1]=quad_U, [2]=quad_V
__device__ float  g_Vt[NDIM * RANK];            // V^T fp32 [8192,64]
__device__ __nv_bfloat16 g_Bu[RANK * NDIM];     // U^T bf16 [64,8192] (MMA B)
__device__ __nv_bfloat16 g_Bv[RANK * NDIM];     // V   bf16 [64,8192] (MMA B)
__device__ __nv_bfloat16 g_Ub16[NDIM * RANK];   // U    bf16 [8192,64] (e1 gather)
__device__ __nv_bfloat16 g_Vt16[NDIM * RANK];   // V^T  bf16 [8192,64] (e1 gather)

__device__ __forceinline__ uint32_t smem_u32(const void* p) {
    uint32_t a;
    asm("{ .reg .u64 t; cvta.to.shared.u64 t, %1; cvt.u32.u64 %0, t; }"
        : "=r"(a) : "l"(p));
    return a;
}

// ======================= prep kernels =======================
// V [64,8192] -> g_Vt fp32 + g_Vt16 bf16 (transpose) + g_Bv bf16 (same layout)
__global__ void prepV_kernel(const float* __restrict__ V) {
    __shared__ float tile[32][33];
    int x = blockIdx.x * 32 + threadIdx.x;   // n
    int y = blockIdx.y * 32 + threadIdx.y;   // r
    float v = V[(size_t)y * NDIM + x];
    tile[threadIdx.y][threadIdx.x] = v;
    g_Bv[(size_t)y * NDIM + x] = __float2bfloat16(v);
    __syncthreads();
    int n = blockIdx.x * 32 + threadIdx.y;
    int r = blockIdx.y * 32 + threadIdx.x;
    float tv = tile[threadIdx.x][threadIdx.y];
    g_Vt[(size_t)n * RANK + r] = tv;
    g_Vt16[(size_t)n * RANK + r] = __float2bfloat16(tv);
    if (blockIdx.x == 0 && blockIdx.y == 0 && threadIdx.y == 0 &&
        threadIdx.x < 3)
        g_acc[threadIdx.x] = 0.0;
}

// U [8192,64] -> g_Bu bf16 (transpose) + g_Ub16 bf16 (same layout)
__global__ void prepU_kernel(const float* __restrict__ U) {
    __shared__ float tile[32][33];
    int i0 = blockIdx.x * 32, r0 = blockIdx.y * 32;
    float u = U[(size_t)(i0 + threadIdx.y) * RANK + r0 + threadIdx.x];
    tile[threadIdx.y][threadIdx.x] = u;
    g_Ub16[(size_t)(i0 + threadIdx.y) * RANK + r0 + threadIdx.x] =
        __float2bfloat16(u);
    __syncthreads();
    g_Bu[(size_t)(r0 + threadIdx.y) * NDIM + i0 + threadIdx.x] =
        __float2bfloat16(tile[threadIdx.x][threadIdx.y]);
}

// ======================= fused quad (HMMA bf16) + e1 =======================
__global__ __launch_bounds__(QTHREADS, 1) void fused_kernel(
    const float* __restrict__ S_U, const float* __restrict__ U,
    const float* __restrict__ S_V, const float* __restrict__ vals,
    const int* __restrict__ rows, const int* __restrict__ cols, int nobs) {
    extern __shared__ char dynsmem[];
    __shared__ float wsum[QTHREADS / 32];
    __shared__ float esum[QTHREADS / 32];

    const int t = threadIdx.x;
    const int wid = t >> 5, lane = t & 31;

    const float* S;
    const __nv_bfloat16* Bg;
    const float* Xf;
    int slot;
    if (blockIdx.z == 0) { S = S_U; Bg = g_Bu; Xf = U;    slot = 1; }
    else                 { S = S_V; Bg = g_Bv; Xf = g_Vt; slot = 2; }
    const int i0 = blockIdx.x * BM;
    const int flat = blockIdx.x + 64 * blockIdx.z;   // 0..127 (e1 CTA id)

    uint32_t base = (smem_u32(dynsmem) + 1023u) & ~1023u;
    uint32_t Abuf[2] = { base, base + A_TILE };
    uint32_t Bbuf[2] = { base + 2 * A_TILE, base + 2 * A_TILE + B_TILE };

    // ---- per-thread staging coordinates ----
    uint32_t a_sts[8];
    const float* a_ldg[8];
    #pragma unroll
    for (int p = 0; p < 8; p++) {
        int flatc = p * QTHREADS + t;
        int row = flatc >> 4;
        int c = (flatc & 15) * 4;
        a_sts[p] = row * 144 + (flatc & 15) * 8;
        a_ldg[p] = S + (size_t)(i0 + row) * NDIM + c;
    }
    uint32_t b_sts[2];
    const __nv_bfloat16* b_ldg[2];
    #pragma unroll
    for (int p = 0; p < 2; p++) {
        int flatc = p * QTHREADS + t;
        int row = flatc >> 3;
        int c16 = (flatc & 7) * 16;
        b_sts[p] = row * 144 + c16;
        b_ldg[p] = Bg + (size_t)row * NDIM + c16 / 2;
    }

    const uint32_t a_lm = (uint32_t)(wid * 16 + (lane & 15)) * 144 + (lane & 16);
    const uint32_t b_lm = (uint32_t)((lane & 7) + ((lane & 16) >> 1)) * 144 +
                          ((lane & 8) << 1);

    float acc[8][4];
    #pragma unroll
    for (int tn = 0; tn < 8; tn++)
        #pragma unroll
        for (int q = 0; q < 4; q++) acc[tn][q] = 0.f;

    float e1sum = 0.f;
    float4 rA[8];
    uint4  rB[2];

#define LOADC(k0) do {                                                        \
    _Pragma("unroll") for (int p = 0; p < 8; p++)                             \
        rA[p] = __ldcs((const float4*)(a_ldg[p] + (k0)));                     \
    _Pragma("unroll") for (int p = 0; p < 2; p++)                             \
        rB[p] = *(const uint4*)(b_ldg[p] + (k0));                             \
} while (0)

#define STOREC(ab, bb) do {                                                   \
    _Pragma("unroll") for (int p = 0; p < 8; p++) {                           \
        uint32_t lo, hi;                                                      \
        asm("cvt.rn.bf16x2.f32 %0, %1, %2;" : "=r"(lo)                        \
            : "f"(rA[p].y), "f"(rA[p].x));                                    \
        asm("cvt.rn.bf16x2.f32 %0, %1, %2;" : "=r"(hi)                        \
            : "f"(rA[p].w), "f"(rA[p].z));                                    \
        asm volatile("st.shared.v2.b32 [%0], {%1, %2};"                       \
                     :: "r"((ab) + a_sts[p]), "r"(lo), "r"(hi));              \
    }                                                                         \
    _Pragma("unroll") for (int p = 0; p < 2; p++)                             \
        asm volatile("st.shared.v4.b32 [%0], {%1, %2, %3, %4};"               \
                     :: "r"((bb) + b_sts[p]), "r"(rB[p].x), "r"(rB[p].y),     \
                        "r"(rB[p].z), "r"(rB[p].w));                          \
} while (0)

#define COMPUTE(ab, bb) do {                                                  \
    _Pragma("unroll") for (int s = 0; s < 4; s++) {                           \
        uint32_t a[4];                                                        \
        asm volatile("ldmatrix.sync.aligned.m8n8.x4.shared.b16 "              \
                     "{%0,%1,%2,%3}, [%4];"                                   \
                     : "=r"(a[0]), "=r"(a[1]), "=r"(a[2]), "=r"(a[3])         \
                     : "r"((ab) + a_lm + s * 32));                            \
        uint32_t b[4][4];                                                     \
        _Pragma("unroll") for (int j = 0; j < 4; j++)                         \
            asm volatile("ldmatrix.sync.aligned.m8n8.x4.shared.b16 "          \
                         "{%0,%1,%2,%3}, [%4];"                               \
                         : "=r"(b[j][0]), "=r"(b[j][1]),                      \
                           "=r"(b[j][2]), "=r"(b[j][3])                       \
                         : "r"((bb) + b_lm + j * (16 * 144) + s * 32));       \
        _Pragma("unroll") for (int tn = 0; tn < 8; tn++)                      \
            asm volatile("mma.sync.aligned.m16n8k16.row.col.f32.bf16.bf16.f32 " \
                         "{%0,%1,%2,%3}, {%4,%5,%6,%7}, {%8,%9}, "            \
                         "{%0,%1,%2,%3};"                                     \
                         : "+f"(acc[tn][0]), "+f"(acc[tn][1]),                \
                           "+f"(acc[tn][2]), "+f"(acc[tn][3])                 \
                         : "r"(a[0]), "r"(a[1]), "r"(a[2]), "r"(a[3]),        \
                           "r"(b[tn >> 1][(tn & 1) * 2]),                     \
                           "r"(b[tn >> 1][(tn & 1) * 2 + 1]));                \
    }                                                                         \
} while (0)

// one e1 observation: gather two bf16 rows, fp32 dot, accumulate (v-pred)^2
#define E1_STEP(j) do {                                                       \
    int idx = flat * 8192 + (j) * QTHREADS + t;                               \
    if (idx < nobs) {                                                         \
        int r = rows[idx], c = cols[idx];                                     \
        float vv = vals[idx];                                                 \
        const uint4* u4 = (const uint4*)(g_Ub16 + (size_t)r * RANK);          \
        const uint4* v4 = (const uint4*)(g_Vt16 + (size_t)c * RANK);          \
        float s = 0.f;                                                        \
        _Pragma("unroll") for (int q = 0; q < 8; q++) {                       \
            uint4 ua = u4[q];                                                 \
            uint4 vb = v4[q];                                                 \
            const uint32_t* up = &ua.x;                                       \
            const uint32_t* vp = &vb.x;                                       \
            _Pragma("unroll") for (int h = 0; h < 4; h++) {                   \
                float2 fu = __bfloat1622float2(                               \
                    *(const __nv_bfloat162*)&up[h]);                          \
                float2 fv = __bfloat1622float2(                               \
                    *(const __nv_bfloat162*)&vp[h]);                          \
                s = fmaf(fu.x, fv.x, s);                                      \
                s = fmaf(fu.y, fv.y, s);                                      \
            }                                                                 \
        }                                                                     \
        float d = vv - s;                                                     \
        e1sum = fmaf(d, d, e1sum);                                            \
    }                                                                         \
} while (0)

    LOADC(0);
    STOREC(Abuf[0], Bbuf[0]);
    __syncthreads();

    for (int cc = 0; cc < NCH; cc++) {
        int cur = cc & 1, nxt = cur ^ 1;
        if (cc + 1 < NCH) LOADC((size_t)(cc + 1) * BKC);
        if ((cc & 3) == 0) E1_STEP(cc >> 2);          // 32 obs per thread
        COMPUTE(Abuf[cur], Bbuf[cur]);
        if (cc + 1 < NCH) {
            __syncthreads();
            STOREC(Abuf[nxt], Bbuf[nxt]);
            __syncthreads();
        }
    }

    // quad epilogue: partial = sum of D[row][n] * X[row][n]
    const int g = lane >> 2, tg = lane & 3;
    const int r0 = i0 + wid * 16 + g;
    float partial = 0.f;
    #pragma unroll
    for (int tn = 0; tn < 8; tn++) {
        int n = tn * 8 + 2 * tg;
        float2 x0 = *(const float2*)(Xf + (size_t)r0 * RANK + n);
        float2 x1 = *(const float2*)(Xf + (size_t)(r0 + 8) * RANK + n);
        partial = fmaf(acc[tn][0], x0.x, partial);
        partial = fmaf(acc[tn][1], x0.y, partial);
        partial = fmaf(acc[tn][2], x1.x, partial);
        partial = fmaf(acc[tn][3], x1.y, partial);
    }
    #pragma unroll
    for (int o = 16; o; o >>= 1) {
        partial += __shfl_xor_sync(0xffffffffu, partial, o);
        e1sum   += __shfl_xor_sync(0xffffffffu, e1sum, o);
    }
    if (lane == 0) { wsum[wid] = partial; esum[wid] = e1sum; }
    __syncthreads();
    if (t == 0) {
        float s = 0.f, e = 0.f;
        #pragma unroll
        for (int i = 0; i < QTHREADS / 32; i++) { s += wsum[i]; e += esum[i]; }
        atomicAdd(&g_acc[slot], (double)s);
        atomicAdd(&g_acc[0], (double)e);
    }
#undef LOADC
#undef STOREC
#undef COMPUTE
#undef E1_STEP
}

// ======================= finalize =======================
__global__ void finalize_kernel(const float* __restrict__ sigma,
                                float* __restrict__ out, int nobs) {
    double s2 = (double)sigma[0] * (double)sigma[0];
    double E = g_acc[0] / (2.0 * s2) + 0.5 * (g_acc[1] + g_acc[2]) +
               (double)nobs * log(s2);
    out[0] = (float)E;
}

extern "C" void kernel_launch(void* const* d_in, const int* in_sizes, int n_in,
                              void* d_out, int out_size) {
    const float* vals  = (const float*)d_in[0];
    const int*   rows  = (const int*)d_in[1];
    const int*   cols  = (const int*)d_in[2];
    const float* U     = (const float*)d_in[3];
    const float* V     = (const float*)d_in[4];
    const float* sigma = (const float*)d_in[5];
    const float* S_U   = (const float*)d_in[6];
    const float* S_V   = (const float*)d_in[7];
    int nobs = in_sizes[0];
    float* out = (float*)d_out;

    cudaFuncSetAttribute(fused_kernel,
                         cudaFuncAttributeMaxDynamicSharedMemorySize, QSMEM);

    prepV_kernel<<<dim3(NDIM / 32, RANK / 32), dim3(32, 32)>>>(V);
    prepU_kernel<<<dim3(NDIM / 32, RANK / 32), dim3(32, 32)>>>(U);
    fused_kernel<<<dim3(NDIM / BM, 1, 2), QTHREADS, QSMEM>>>(
        S_U, U, S_V, vals, rows, cols, nobs);
    finalize_kernel<<<1, 1>>>(sigma, out, nobs);
}

// round 5
// speedup vs baseline: 2.8150x; 1.1837x over previous
#include <cuda_runtime.h>
#include <cuda_bf16.h>
#include <cstdint>
#include <math.h>

#define NDIM 8192
#define RANK 64
#define BM 128
#define BKC 64
#define NCH (NDIM / BKC)       // 128 K-chunks
#define QTHREADS 512
#define A_TILE (BM * 144)
#define B_TILE (RANK * 144)
#define QSMEM (1024 + 3 * (A_TILE + B_TILE))

// ---- device scratch (allocation-free rule) ----
__device__ double g_acc[3];                     // [0]=E1, [1]=quad_U, [2]=quad_V
__device__ float  g_Vt[NDIM * RANK];            // V^T fp32 [8192,64]
__device__ __nv_bfloat16 g_Bu[RANK * NDIM];     // U^T bf16 [64,8192] (MMA B)
__device__ __nv_bfloat16 g_Bv[RANK * NDIM];     // V   bf16 [64,8192] (MMA B)
__device__ __nv_bfloat16 g_Ub16[NDIM * RANK];   // U    bf16 [8192,64] (e1 gather)
__device__ __nv_bfloat16 g_Vt16[NDIM * RANK];   // V^T  bf16 [8192,64] (e1 gather)

__device__ __forceinline__ uint32_t smem_u32(const void* p) {
    uint32_t a;
    asm("{ .reg .u64 t; cvta.to.shared.u64 t, %1; cvt.u32.u64 %0, t; }"
        : "=r"(a) : "l"(p));
    return a;
}

// ======================= prep (fused, grid.z selects) =======================
__global__ void prep_kernel(const float* __restrict__ V,
                            const float* __restrict__ U) {
    __shared__ float tile[32][33];
    if (blockIdx.z == 0) {
        // V [64,8192] -> g_Vt fp32 + g_Vt16 bf16 (transpose) + g_Bv bf16
        int x = blockIdx.x * 32 + threadIdx.x;   // n
        int y = blockIdx.y * 32 + threadIdx.y;   // r
        float v = V[(size_t)y * NDIM + x];
        tile[threadIdx.y][threadIdx.x] = v;
        g_Bv[(size_t)y * NDIM + x] = __float2bfloat16(v);
        __syncthreads();
        int n = blockIdx.x * 32 + threadIdx.y;
        int r = blockIdx.y * 32 + threadIdx.x;
        float tv = tile[threadIdx.x][threadIdx.y];
        g_Vt[(size_t)n * RANK + r] = tv;
        g_Vt16[(size_t)n * RANK + r] = __float2bfloat16(tv);
        if (blockIdx.x == 0 && blockIdx.y == 0 && threadIdx.y == 0 &&
            threadIdx.x < 3)
            g_acc[threadIdx.x] = 0.0;
    } else {
        // U [8192,64] -> g_Bu bf16 (transpose) + g_Ub16 bf16
        int i0 = blockIdx.x * 32, r0 = blockIdx.y * 32;
        float u = U[(size_t)(i0 + threadIdx.y) * RANK + r0 + threadIdx.x];
        tile[threadIdx.y][threadIdx.x] = u;
        g_Ub16[(size_t)(i0 + threadIdx.y) * RANK + r0 + threadIdx.x] =
            __float2bfloat16(u);
        __syncthreads();
        g_Bu[(size_t)(r0 + threadIdx.y) * NDIM + i0 + threadIdx.x] =
            __float2bfloat16(tile[threadIdx.x][threadIdx.y]);
    }
}

// ======================= fused quad (HMMA bf16) + e1 =======================
// 512 threads, 16 warps: warp (wm = wid&7) handles M rows wm*16..+15,
// (wn = wid>>3) handles N half wn*32..+31. 2-chunk register prefetch,
// 3 smem buffers, 1 syncthreads per chunk.
__global__ __launch_bounds__(QTHREADS, 1) void fused_kernel(
    const float* __restrict__ S_U, const float* __restrict__ U,
    const float* __restrict__ S_V, const float* __restrict__ vals,
    const int* __restrict__ rows, const int* __restrict__ cols, int nobs) {
    extern __shared__ char dynsmem[];
    __shared__ float wsum[QTHREADS / 32];
    __shared__ float esum[QTHREADS / 32];

    const int t = threadIdx.x;
    const int wid = t >> 5, lane = t & 31;
    const int wm = wid & 7, wn = wid >> 3;

    const float* S;
    const __nv_bfloat16* Bg;
    const float* Xf;
    int slot;
    if (blockIdx.z == 0) { S = S_U; Bg = g_Bu; Xf = U;    slot = 1; }
    else                 { S = S_V; Bg = g_Bv; Xf = g_Vt; slot = 2; }
    const int i0 = blockIdx.x * BM;
    const int ctaid = blockIdx.x + 64 * blockIdx.z;   // 0..127

    uint32_t base = (smem_u32(dynsmem) + 1023u) & ~1023u;
    uint32_t bA = base;                          // compute target
    uint32_t bB = base + (A_TILE + B_TILE);      // store target
    uint32_t bC = base + 2 * (A_TILE + B_TILE);  // spare

    // ---- staging coordinates (4 A-passes, 1 B-pass per thread) ----
    const float* a_base = S + (size_t)(i0 + (t >> 4)) * NDIM + (t & 15) * 4;
    const uint32_t a_st = (uint32_t)(t >> 4) * 144 + (t & 15) * 8;
    const __nv_bfloat16* b_base = Bg + (size_t)(t >> 3) * NDIM + (t & 7) * 8;
    const uint32_t b_st = (uint32_t)(t >> 3) * 144 + (t & 7) * 16;

    // ldmatrix lane offsets
    const uint32_t a_lm = (uint32_t)(wm * 16 + (lane & 15)) * 144 + (lane & 16);
    const uint32_t b_lm = (uint32_t)((lane & 7) + ((lane & 16) >> 1) + wn * 32) *
                              144 + ((lane & 8) << 1);

    float acc[4][4];
    #pragma unroll
    for (int tn = 0; tn < 4; tn++)
        #pragma unroll
        for (int q = 0; q < 4; q++) acc[tn][q] = 0.f;

    float e1sum = 0.f;
    float4 rAx[4], rAy[4];
    uint4  rBx, rBy;

#define LOADC(k0, RA, RB) do {                                                \
    _Pragma("unroll") for (int p = 0; p < 4; p++)                             \
        RA[p] = __ldcs((const float4*)(a_base + (k0) +                        \
                                       (size_t)p * 32 * NDIM));               \
    RB = *(const uint4*)(b_base + (k0));                                      \
} while (0)

#define STOREC(buf, RA, RB) do {                                              \
    _Pragma("unroll") for (int p = 0; p < 4; p++) {                           \
        uint32_t lo, hi;                                                      \
        asm("cvt.rn.bf16x2.f32 %0, %1, %2;" : "=r"(lo)                        \
            : "f"(RA[p].y), "f"(RA[p].x));                                    \
        asm("cvt.rn.bf16x2.f32 %0, %1, %2;" : "=r"(hi)                        \
            : "f"(RA[p].w), "f"(RA[p].z));                                    \
        asm volatile("st.shared.v2.b32 [%0], {%1, %2};"                       \
                     :: "r"((buf) + a_st + p * (32 * 144)),                   \
                        "r"(lo), "r"(hi));                                    \
    }                                                                         \
    asm volatile("st.shared.v4.b32 [%0], {%1, %2, %3, %4};"                   \
                 :: "r"((buf) + A_TILE + b_st), "r"(RB.x), "r"(RB.y),         \
                    "r"(RB.z), "r"(RB.w));                                    \
} while (0)

#define COMPUTE(buf) do {                                                     \
    uint32_t ab = (buf), bb = (buf) + A_TILE;                                 \
    _Pragma("unroll") for (int s = 0; s < 4; s++) {                           \
        uint32_t a[4];                                                        \
        asm volatile("ldmatrix.sync.aligned.m8n8.x4.shared.b16 "              \
                     "{%0,%1,%2,%3}, [%4];"                                   \
                     : "=r"(a[0]), "=r"(a[1]), "=r"(a[2]), "=r"(a[3])         \
                     : "r"(ab + a_lm + s * 32));                              \
        uint32_t b[2][4];                                                     \
        _Pragma("unroll") for (int j = 0; j < 2; j++)                         \
            asm volatile("ldmatrix.sync.aligned.m8n8.x4.shared.b16 "          \
                         "{%0,%1,%2,%3}, [%4];"                               \
                         : "=r"(b[j][0]), "=r"(b[j][1]),                      \
                           "=r"(b[j][2]), "=r"(b[j][3])                       \
                         : "r"(bb + b_lm + j * (16 * 144) + s * 32));         \
        _Pragma("unroll") for (int tn = 0; tn < 4; tn++)                      \
            asm volatile("mma.sync.aligned.m16n8k16.row.col.f32.bf16.bf16.f32 " \
                         "{%0,%1,%2,%3}, {%4,%5,%6,%7}, {%8,%9}, "            \
                         "{%0,%1,%2,%3};"                                     \
                         : "+f"(acc[tn][0]), "+f"(acc[tn][1]),                \
                           "+f"(acc[tn][2]), "+f"(acc[tn][3])                 \
                         : "r"(a[0]), "r"(a[1]), "r"(a[2]), "r"(a[3]),        \
                           "r"(b[tn >> 1][(tn & 1) * 2]),                     \
                           "r"(b[tn >> 1][(tn & 1) * 2 + 1]));                \
    }                                                                         \
} while (0)

#define E1_STEP(j) do {                                                       \
    int idx = ctaid * 8192 + (j) * QTHREADS + t;                              \
    if (idx < nobs) {                                                         \
        int r = rows[idx], c = cols[idx];                                     \
        float vv = vals[idx];                                                 \
        const uint4* u4 = (const uint4*)(g_Ub16 + (size_t)r * RANK);          \
        const uint4* v4 = (const uint4*)(g_Vt16 + (size_t)c * RANK);          \
        float s = 0.f;                                                        \
        _Pragma("unroll") for (int q = 0; q < 8; q++) {                       \
            uint4 ua = u4[q];                                                 \
            uint4 vb = v4[q];                                                 \
            const uint32_t* up = &ua.x;                                       \
            const uint32_t* vp = &vb.x;                                       \
            _Pragma("unroll") for (int h = 0; h < 4; h++) {                   \
                float2 fu = __bfloat1622float2(                               \
                    *(const __nv_bfloat162*)&up[h]);                          \
                float2 fv = __bfloat1622float2(                               \
                    *(const __nv_bfloat162*)&vp[h]);                          \
                s = fmaf(fu.x, fv.x, s);                                      \
                s = fmaf(fu.y, fv.y, s);                                      \
            }                                                                 \
        }                                                                     \
        float d = vv - s;                                                     \
        e1sum = fmaf(d, d, e1sum);                                            \
    }                                                                         \
} while (0)

    // prologue: chunks 0,1 in registers; chunk0 -> bA
    LOADC(0, rAx, rBx);
    LOADC(BKC, rAy, rBy);
    STOREC(bA, rAx, rBx);
    __syncthreads();

    // steady state (double-step): per chunk cc —
    //   load(cc+2) / compute(buf[cc%3]) / store(cc+1 -> buf[(cc+1)%3]) / sync
    for (int cc = 0; cc < NCH; cc += 2) {
        if (cc + 2 < NCH) LOADC((size_t)(cc + 2) * BKC, rAx, rBx);
        if ((cc & 7) == 0) E1_STEP(cc >> 3);     // 16 obs per thread total
        COMPUTE(bA);
        STOREC(bB, rAy, rBy);                    // cc+1 < NCH always
        __syncthreads();
        if (cc + 3 < NCH) LOADC((size_t)(cc + 3) * BKC, rAy, rBy);
        COMPUTE(bB);
        if (cc + 2 < NCH) STOREC(bC, rAx, rBx);
        __syncthreads();
        uint32_t tmp = bA; bA = bC; bC = bB; bB = tmp;
    }

    // quad epilogue: partial = sum of D[row][n] * X[row][n]
    const int g = lane >> 2, tg = lane & 3;
    const int r0 = i0 + wm * 16 + g;
    float partial = 0.f;
    #pragma unroll
    for (int tn = 0; tn < 4; tn++) {
        int n = wn * 32 + tn * 8 + 2 * tg;
        float2 x0 = *(const float2*)(Xf + (size_t)r0 * RANK + n);
        float2 x1 = *(const float2*)(Xf + (size_t)(r0 + 8) * RANK + n);
        partial = fmaf(acc[tn][0], x0.x, partial);
        partial = fmaf(acc[tn][1], x0.y, partial);
        partial = fmaf(acc[tn][2], x1.x, partial);
        partial = fmaf(acc[tn][3], x1.y, partial);
    }
    #pragma unroll
    for (int o = 16; o; o >>= 1) {
        partial += __shfl_xor_sync(0xffffffffu, partial, o);
        e1sum   += __shfl_xor_sync(0xffffffffu, e1sum, o);
    }
    if (lane == 0) { wsum[wid] = partial; esum[wid] = e1sum; }
    __syncthreads();
    if (t == 0) {
        float s = 0.f, e = 0.f;
        #pragma unroll
        for (int i = 0; i < QTHREADS / 32; i++) { s += wsum[i]; e += esum[i]; }
        atomicAdd(&g_acc[slot], (double)s);
        atomicAdd(&g_acc[0], (double)e);
    }
#undef LOADC
#undef STOREC
#undef COMPUTE
#undef E1_STEP
}

// ======================= finalize =======================
__global__ void finalize_kernel(const float* __restrict__ sigma,
                                float* __restrict__ out, int nobs) {
    double s2 = (double)sigma[0] * (double)sigma[0];
    double E = g_acc[0] / (2.0 * s2) + 0.5 * (g_acc[1] + g_acc[2]) +
               (double)nobs * log(s2);
    out[0] = (float)E;
}

extern "C" void kernel_launch(void* const* d_in, const int* in_sizes, int n_in,
                              void* d_out, int out_size) {
    const float* vals  = (const float*)d_in[0];
    const int*   rows  = (const int*)d_in[1];
    const int*   cols  = (const int*)d_in[2];
    const float* U     = (const float*)d_in[3];
    const float* V     = (const float*)d_in[4];
    const float* sigma = (const float*)d_in[5];
    const float* S_U   = (const float*)d_in[6];
    const float* S_V   = (const float*)d_in[7];
    int nobs = in_sizes[0];
    float* out = (float*)d_out;

    cudaFuncSetAttribute(fused_kernel,
                         cudaFuncAttributeMaxDynamicSharedMemorySize, QSMEM);

    prep_kernel<<<dim3(NDIM / 32, RANK / 32, 2), dim3(32, 32)>>>(V, U);
    fused_kernel<<<dim3(NDIM / BM, 1, 2), QTHREADS, QSMEM>>>(
        S_U, U, S_V, vals, rows, cols, nobs);
    finalize_kernel<<<1, 1>>>(sigma, out, nobs);
}